// round 10
// baseline (speedup 1.0000x reference)
#include <cuda_runtime.h>
#include <cuda_bf16.h>
#include <cstdint>

#define BATCH   8192
#define MDIM    512
#define HDIM    1024
#define ROWS    (2 * BATCH)          // 16384 stacked rows (anchor ; positive)

// ---------------------------------------------------------------------------
// Device scratch — activations live as split bf16 hi/lo planes
// ---------------------------------------------------------------------------
__device__ __align__(256) __nv_bfloat16 g_Xhi [(size_t)ROWS * MDIM];
__device__ __align__(256) __nv_bfloat16 g_Xlo [(size_t)ROWS * MDIM];
__device__ __align__(256) __nv_bfloat16 g_A0hi[(size_t)ROWS * HDIM];
__device__ __align__(256) __nv_bfloat16 g_A0lo[(size_t)ROWS * HDIM];
__device__ __align__(256) __nv_bfloat16 g_A1hi[(size_t)ROWS * HDIM];
__device__ __align__(256) __nv_bfloat16 g_A1lo[(size_t)ROWS * HDIM];
#define WTOTAL 5767168   // 512*1024 + 5*1024*1024
__device__ __align__(256) __nv_bfloat16 g_Whi[WTOTAL];
__device__ __align__(256) __nv_bfloat16 g_Wlo[WTOTAL];
__device__ int g_mask_byte_flag;

// ---------------------------------------------------------------------------
// Helpers (compute_103-legal)
// ---------------------------------------------------------------------------
__device__ __forceinline__ uint32_t smem_u32(const void* p) {
    uint32_t a;
    asm("{ .reg .u64 t; cvta.to.shared.u64 t, %1; cvt.u32.u64 %0, t; }" : "=r"(a) : "l"(p));
    return a;
}
__device__ __forceinline__ void ldsm_x4(uint32_t (&r)[4], uint32_t a) {
    asm volatile("ldmatrix.sync.aligned.m8n8.x4.shared.b16 {%0,%1,%2,%3}, [%4];"
                 : "=r"(r[0]), "=r"(r[1]), "=r"(r[2]), "=r"(r[3]) : "r"(a));
}
__device__ __forceinline__ void mma_bf16(float (&d)[4], const uint32_t (&a)[4],
                                         uint32_t b0, uint32_t b1) {
    asm volatile("mma.sync.aligned.m16n8k16.row.col.f32.bf16.bf16.f32 "
                 "{%0,%1,%2,%3}, {%4,%5,%6,%7}, {%8,%9}, {%0,%1,%2,%3};"
                 : "+f"(d[0]), "+f"(d[1]), "+f"(d[2]), "+f"(d[3])
                 : "r"(a[0]), "r"(a[1]), "r"(a[2]), "r"(a[3]), "r"(b0), "r"(b1));
}
#define CP_ASYNC16(dst, src) \
    asm volatile("cp.async.cg.shared.global [%0], [%1], 16;" :: "r"(dst), "l"(src))
#define CP_COMMIT()  asm volatile("cp.async.commit_group;" ::: "memory")
#define CP_WAIT1()   asm volatile("cp.async.wait_group 1;" ::: "memory")
#define SWZ128(o) ((o) ^ (((o) >> 3) & 0x70))
#define SWZ64(o)  ((o) ^ (((o) >> 3) & 0x30))

// ---------------------------------------------------------------------------
// Mask dtype detection + split input build (proven)
// ---------------------------------------------------------------------------
__global__ void detect_mask_kernel(const unsigned char* __restrict__ m) {
    __shared__ int s_gt1, s_odd;
    if (threadIdx.x == 0) { s_gt1 = 0; s_odd = 0; }
    __syncthreads();
    int gt1 = 0, odd = 0;
    for (int o = threadIdx.x; o < 65536; o += blockDim.x) {
        unsigned char b = m[o];
        if (b > 1) gt1 = 1;
        if ((o & 3) && b) odd = 1;
    }
    if (gt1) atomicOr(&s_gt1, 1);
    if (odd) atomicOr(&s_odd, 1);
    __syncthreads();
    if (threadIdx.x == 0) g_mask_byte_flag = (!s_gt1 && s_odd) ? 1 : 0;
}

__device__ __forceinline__ void split_store(__nv_bfloat16* hi, __nv_bfloat16* lo,
                                            size_t idx, float v) {
    __nv_bfloat16 h = __float2bfloat16(v);
    hi[idx] = h;
    lo[idx] = __float2bfloat16(v - __bfloat162float(h));
}

__global__ void build_x_kernel(const float* __restrict__ anchor,
                               const float* __restrict__ rnd,
                               const void*  __restrict__ mask) {
    int i = blockIdx.x * blockDim.x + threadIdx.x;
    const int n = BATCH * MDIM;
    if (i >= n) return;
    float a = anchor[i];
    split_store(g_Xhi, g_Xlo, i, a);
    bool m;
    if (g_mask_byte_flag) m = ((const unsigned char*)mask)[i] != 0;
    else                  m = ((const unsigned int*)mask)[i] != 0u;
    split_store(g_Xhi, g_Xlo, (size_t)n + i, m ? rnd[i] : a);
}

// ---------------------------------------------------------------------------
// Fused weight transpose + bf16 split for ALL 6 layers (grid.z = layer)
// ---------------------------------------------------------------------------
__global__ void wsplit_all_kernel(const float* __restrict__ enc_w0,
                                  const float* __restrict__ enc_w,
                                  const float* __restrict__ head_w) {
    const size_t HH = (size_t)HDIM * HDIM;
    const int z = blockIdx.z;
    const float* W;
    size_t off;
    int K;
    if (z == 0)      { W = enc_w0;                 off = 0;                      K = MDIM; }
    else if (z <= 3) { W = enc_w  + (z - 1) * HH;  off = 524288 + (z - 1) * HH;  K = HDIM; }
    else             { W = head_w + (z - 4) * HH;  off = 524288 + (z - 1) * HH;  K = HDIM; }
    if (blockIdx.y * 32 >= (unsigned)K) return;

    __shared__ float t[32][33];
    int nb = blockIdx.x * 32, kb = blockIdx.y * 32;
    int tx = threadIdx.x, ty = threadIdx.y;   // (32, 8)
    for (int r = ty; r < 32; r += 8)
        t[r][tx] = W[(size_t)(kb + r) * HDIM + nb + tx];
    __syncthreads();
    __nv_bfloat16* hi = g_Whi + off;
    __nv_bfloat16* lo = g_Wlo + off;
    for (int r = ty; r < 32; r += 8) {
        float v = t[tx][r];
        __nv_bfloat16 h = __float2bfloat16(v);
        __nv_bfloat16 l = __float2bfloat16(v - __bfloat162float(h));
        size_t o = (size_t)(nb + r) * K + kb + tx;
        hi[o] = h;  lo[o] = l;
    }
}

// ---------------------------------------------------------------------------
// HMMA GEMM: CTA 64x128, 128 threads = 4 warps (2m x 2n), warp tile 32x64,
// BK=32, 3-stage cp.async pipeline, ONE __syncthreads per chunk.
//   acc = Ah@Bh + Ah@Bl + Al@Bh
// SMEM stage (SW64, 64B rows): Ah(4K) Al(4K) Bh(8K) Bl(8K) = 24KB;
//   3 stages = 72KB  =>  THREE CTAs co-resident per SM (12 warps, 3/SMSP).
// ---------------------------------------------------------------------------
#define AH_OFF 0
#define AL_OFF 4096
#define BH_OFF 8192
#define BL_OFF 16384
#define STAGE_STRIDE 24576
#define SM_TOTAL (3 * STAGE_STRIDE)   // 73728

__global__ void __launch_bounds__(128, 3)
gemm_hmma(const __nv_bfloat16* __restrict__ Ahi,
          const __nv_bfloat16* __restrict__ Alo,
          const __nv_bfloat16* __restrict__ Bhi,
          const __nv_bfloat16* __restrict__ Blo,
          const float* __restrict__ bias,
          __nv_bfloat16* __restrict__ Chi,
          __nv_bfloat16* __restrict__ Clo,
          float* __restrict__ Cf32,
          int K, int writeF32) {
    extern __shared__ char smem[];
    const uint32_t sb = smem_u32(smem);
    const int tid  = threadIdx.x;
    const int wid  = tid >> 5, lane = tid & 31;
    const int wm   = wid & 1;          // warp m (2)
    const int wn   = wid >> 1;         // warp n (2)
    const int mb   = blockIdx.y, nb = blockIdx.x;

    const __nv_bfloat16* Ah = Ahi + (size_t)mb * 64 * K;
    const __nv_bfloat16* Al = Alo + (size_t)mb * 64 * K;
    const __nv_bfloat16* Bh = Bhi + (size_t)nb * 128 * K;
    const __nv_bfloat16* Bl = Blo + (size_t)nb * 128 * K;

    // loader mapping (BK=32, 64B rows): r = tid>>2, g16 = (tid&3)*16 bytes
    const int g16e = (tid & 3) * 8;    // element offset within 32-col chunk

    float acc[2][8][4];
#pragma unroll
    for (int mt = 0; mt < 2; mt++)
#pragma unroll
        for (int nt = 0; nt < 8; nt++)
#pragma unroll
            for (int q = 0; q < 4; q++) acc[mt][nt][q] = 0.f;

    const int nchunks = K >> 5;

    auto issue_stage = [&](int c, int s) {
        const uint32_t bs = sb + s * STAGE_STRIDE;
        const int cc = c * 32 + g16e;
        // A planes: 64 rows x 4 groups = 256 tasks / 128 thr = 2 iters
#pragma unroll
        for (int j = 0; j < 2; j++) {
            int r = (tid + 128 * j) >> 2;
            uint32_t sw = SWZ64((uint32_t)(r * 64 + (tid & 3) * 16));
            CP_ASYNC16(bs + AH_OFF + sw, (const char*)(Ah + (size_t)r * K + cc));
            CP_ASYNC16(bs + AL_OFF + sw, (const char*)(Al + (size_t)r * K + cc));
        }
        // B planes: 128 rows x 4 groups = 512 tasks / 128 thr = 4 iters
#pragma unroll
        for (int j = 0; j < 4; j++) {
            int r = (tid + 128 * j) >> 2;
            uint32_t sw = SWZ64((uint32_t)(r * 64 + (tid & 3) * 16));
            CP_ASYNC16(bs + BH_OFF + sw, (const char*)(Bh + (size_t)r * K + cc));
            CP_ASYNC16(bs + BL_OFF + sw, (const char*)(Bl + (size_t)r * K + cc));
        }
    };

    issue_stage(0, 0); CP_COMMIT();
    if (nchunks > 1) issue_stage(1, 1);
    CP_COMMIT();

    const int krow = lane & 15;
    const int kc16 = (lane >> 4) * 16;   // byte offset of 8-col half

    for (int c = 0; c < nchunks; c++) {
        CP_WAIT1();              // stage c resident (stage c+1 may be pending)
        __syncthreads();         // all warps done reading stage c-1 (== c+2 slot)

        if (c + 2 < nchunks) issue_stage(c + 2, (c + 2) % 3);
        CP_COMMIT();             // uniform group accounting

        const uint32_t bufp = sb + (c % 3) * STAGE_STRIDE;
#pragma unroll
        for (int ks = 0; ks < 2; ks++) {
            const int kcB = ks * 32 + kc16;
            uint32_t ah[2][4], al[2][4];
#pragma unroll
            for (int mt = 0; mt < 2; mt++) {
                uint32_t off = (uint32_t)((wm * 32 + mt * 16 + krow) * 64) + kcB;
                ldsm_x4(ah[mt], bufp + AH_OFF + SWZ64(off));
                ldsm_x4(al[mt], bufp + AL_OFF + SWZ64(off));
            }
            uint32_t bh[8][2], bl[8][2];
#pragma unroll
            for (int bt = 0; bt < 4; bt++) {
                uint32_t off = (uint32_t)((wn * 64 + bt * 16 + krow) * 64) + kcB;
                uint32_t r[4], r2[4];
                ldsm_x4(r,  bufp + BH_OFF + SWZ64(off));
                ldsm_x4(r2, bufp + BL_OFF + SWZ64(off));
                bh[2*bt][0] = r[0];  bh[2*bt+1][0] = r[1];
                bh[2*bt][1] = r[2];  bh[2*bt+1][1] = r[3];
                bl[2*bt][0] = r2[0]; bl[2*bt+1][0] = r2[1];
                bl[2*bt][1] = r2[2]; bl[2*bt+1][1] = r2[3];
            }
#pragma unroll
            for (int mt = 0; mt < 2; mt++)
#pragma unroll
                for (int nt = 0; nt < 8; nt++) {
                    mma_bf16(acc[mt][nt], ah[mt], bh[nt][0], bh[nt][1]);
                    mma_bf16(acc[mt][nt], ah[mt], bl[nt][0], bl[nt][1]);
                    mma_bf16(acc[mt][nt], al[mt], bh[nt][0], bh[nt][1]);
                }
        }
    }

    // ---- epilogue: relu(acc+bias); split bf16 planes or fp32 ----
    const int rbase = mb * 64 + wm * 32 + (lane >> 2);
    const int cbase = nb * 128 + wn * 64 + 2 * (lane & 3);
#pragma unroll
    for (int mt = 0; mt < 2; mt++)
#pragma unroll
        for (int nt = 0; nt < 8; nt++) {
            const int c0 = cbase + nt * 8;
            const float b0v = bias[c0], b1v = bias[c0 + 1];
            float v00 = fmaxf(acc[mt][nt][0] + b0v, 0.f);
            float v01 = fmaxf(acc[mt][nt][1] + b1v, 0.f);
            float v10 = fmaxf(acc[mt][nt][2] + b0v, 0.f);
            float v11 = fmaxf(acc[mt][nt][3] + b1v, 0.f);
            const size_t o0 = (size_t)(rbase + mt * 16)     * HDIM + c0;
            const size_t o1 = (size_t)(rbase + mt * 16 + 8) * HDIM + c0;
            if (writeF32) {
                *(float2*)(Cf32 + o0) = make_float2(v00, v01);
                *(float2*)(Cf32 + o1) = make_float2(v10, v11);
            } else {
                __nv_bfloat16 h00 = __float2bfloat16(v00);
                __nv_bfloat16 h01 = __float2bfloat16(v01);
                __nv_bfloat16 h10 = __float2bfloat16(v10);
                __nv_bfloat16 h11 = __float2bfloat16(v11);
                __nv_bfloat162 l0, l1;
                l0.x = __float2bfloat16(v00 - __bfloat162float(h00));
                l0.y = __float2bfloat16(v01 - __bfloat162float(h01));
                l1.x = __float2bfloat16(v10 - __bfloat162float(h10));
                l1.y = __float2bfloat16(v11 - __bfloat162float(h11));
                *(__nv_bfloat162*)(Chi + o0) = make_bfloat162(h00, h01);
                *(__nv_bfloat162*)(Chi + o1) = make_bfloat162(h10, h11);
                *(__nv_bfloat162*)(Clo + o0) = l0;
                *(__nv_bfloat162*)(Clo + o1) = l1;
            }
        }
}

// ---------------------------------------------------------------------------
// kernel_launch
// ---------------------------------------------------------------------------
extern "C" void kernel_launch(void* const* d_in, const int* in_sizes, int n_in,
                              void* d_out, int out_size) {
    const float* anchor = (const float*)d_in[0];
    const float* rnd    = (const float*)d_in[1];
    const void*  mask   = d_in[2];
    const float* enc_w0 = (const float*)d_in[3];
    const float* enc_b0 = (const float*)d_in[4];
    const float* enc_w  = (const float*)d_in[5];
    const float* enc_b  = (const float*)d_in[6];
    const float* head_w = (const float*)d_in[7];
    const float* head_b = (const float*)d_in[8];
    float* out = (float*)d_out;

    __nv_bfloat16 *Xhi, *Xlo, *A0hi, *A0lo, *A1hi, *A1lo, *Whi, *Wlo;
    cudaGetSymbolAddress((void**)&Xhi,  g_Xhi);
    cudaGetSymbolAddress((void**)&Xlo,  g_Xlo);
    cudaGetSymbolAddress((void**)&A0hi, g_A0hi);
    cudaGetSymbolAddress((void**)&A0lo, g_A0lo);
    cudaGetSymbolAddress((void**)&A1hi, g_A1hi);
    cudaGetSymbolAddress((void**)&A1lo, g_A1lo);
    cudaGetSymbolAddress((void**)&Whi,  g_Whi);
    cudaGetSymbolAddress((void**)&Wlo,  g_Wlo);

    cudaFuncSetAttribute(gemm_hmma, cudaFuncAttributeMaxDynamicSharedMemorySize, SM_TOTAL);

    detect_mask_kernel<<<1, 256>>>((const unsigned char*)mask);
    const int nSel = BATCH * MDIM;
    build_x_kernel<<<(nSel + 255) / 256, 256>>>(anchor, rnd, mask);

    dim3 wb(32, 8);
    wsplit_all_kernel<<<dim3(HDIM / 32, HDIM / 32, 6), wb>>>(enc_w0, enc_w, head_w);

    const size_t HH = (size_t)HDIM * HDIM;
    const size_t woff[6] = {0, 524288, 524288 + HH, 524288 + 2*HH, 524288 + 3*HH, 524288 + 4*HH};

    dim3 grid(HDIM / 128, ROWS / 64);   // (8, 256) = 2048 CTAs
    gemm_hmma<<<grid, 128, SM_TOTAL>>>(Xhi,  Xlo,  Whi + woff[0], Wlo + woff[0], enc_b0,          A0hi, A0lo, nullptr, MDIM, 0);
    gemm_hmma<<<grid, 128, SM_TOTAL>>>(A0hi, A0lo, Whi + woff[1], Wlo + woff[1], enc_b + 0*HDIM,  A1hi, A1lo, nullptr, HDIM, 0);
    gemm_hmma<<<grid, 128, SM_TOTAL>>>(A1hi, A1lo, Whi + woff[2], Wlo + woff[2], enc_b + 1*HDIM,  A0hi, A0lo, nullptr, HDIM, 0);
    gemm_hmma<<<grid, 128, SM_TOTAL>>>(A0hi, A0lo, Whi + woff[3], Wlo + woff[3], enc_b + 2*HDIM,  A1hi, A1lo, nullptr, HDIM, 0);
    gemm_hmma<<<grid, 128, SM_TOTAL>>>(A1hi, A1lo, Whi + woff[4], Wlo + woff[4], head_b + 0*HDIM, A0hi, A0lo, nullptr, HDIM, 0);
    gemm_hmma<<<grid, 128, SM_TOTAL>>>(A0hi, A0lo, Whi + woff[5], Wlo + woff[5], head_b + 1*HDIM, nullptr, nullptr, out, HDIM, 1);
}

// round 11
// speedup vs baseline: 1.0777x; 1.0777x over previous
#include <cuda_runtime.h>
#include <cuda_bf16.h>
#include <cstdint>

#define BATCH   8192
#define MDIM    512
#define HDIM    1024
#define ROWS    (2 * BATCH)          // 16384 stacked rows (anchor ; positive)

// ---------------------------------------------------------------------------
// Device scratch — activations live as split bf16 hi/lo planes
// ---------------------------------------------------------------------------
__device__ __align__(256) __nv_bfloat16 g_Xhi [(size_t)ROWS * MDIM];
__device__ __align__(256) __nv_bfloat16 g_Xlo [(size_t)ROWS * MDIM];
__device__ __align__(256) __nv_bfloat16 g_A0hi[(size_t)ROWS * HDIM];
__device__ __align__(256) __nv_bfloat16 g_A0lo[(size_t)ROWS * HDIM];
__device__ __align__(256) __nv_bfloat16 g_A1hi[(size_t)ROWS * HDIM];
__device__ __align__(256) __nv_bfloat16 g_A1lo[(size_t)ROWS * HDIM];
#define WTOTAL 5767168   // 512*1024 + 5*1024*1024
__device__ __align__(256) __nv_bfloat16 g_Whi[WTOTAL];
__device__ __align__(256) __nv_bfloat16 g_Wlo[WTOTAL];
__device__ int g_mask_byte_flag;

// ---------------------------------------------------------------------------
// Helpers (compute_103-legal)
// ---------------------------------------------------------------------------
__device__ __forceinline__ uint32_t smem_u32(const void* p) {
    uint32_t a;
    asm("{ .reg .u64 t; cvta.to.shared.u64 t, %1; cvt.u32.u64 %0, t; }" : "=r"(a) : "l"(p));
    return a;
}
__device__ __forceinline__ void ldsm_x4(uint32_t (&r)[4], uint32_t a) {
    asm volatile("ldmatrix.sync.aligned.m8n8.x4.shared.b16 {%0,%1,%2,%3}, [%4];"
                 : "=r"(r[0]), "=r"(r[1]), "=r"(r[2]), "=r"(r[3]) : "r"(a));
}
__device__ __forceinline__ void mma_bf16(float (&d)[4], const uint32_t (&a)[4],
                                         uint32_t b0, uint32_t b1) {
    asm volatile("mma.sync.aligned.m16n8k16.row.col.f32.bf16.bf16.f32 "
                 "{%0,%1,%2,%3}, {%4,%5,%6,%7}, {%8,%9}, {%0,%1,%2,%3};"
                 : "+f"(d[0]), "+f"(d[1]), "+f"(d[2]), "+f"(d[3])
                 : "r"(a[0]), "r"(a[1]), "r"(a[2]), "r"(a[3]), "r"(b0), "r"(b1));
}
#define CP_ASYNC16(dst, src) \
    asm volatile("cp.async.cg.shared.global [%0], [%1], 16;" :: "r"(dst), "l"(src))
#define CP_COMMIT()  asm volatile("cp.async.commit_group;" ::: "memory")
#define CP_WAIT1()   asm volatile("cp.async.wait_group 1;" ::: "memory")
#define SWZ128(o) ((o) ^ (((o) >> 3) & 0x70))

// ---------------------------------------------------------------------------
// Mask dtype detection + split input build (proven)
// ---------------------------------------------------------------------------
__global__ void detect_mask_kernel(const unsigned char* __restrict__ m) {
    __shared__ int s_gt1, s_odd;
    if (threadIdx.x == 0) { s_gt1 = 0; s_odd = 0; }
    __syncthreads();
    int gt1 = 0, odd = 0;
    for (int o = threadIdx.x; o < 65536; o += blockDim.x) {
        unsigned char b = m[o];
        if (b > 1) gt1 = 1;
        if ((o & 3) && b) odd = 1;
    }
    if (gt1) atomicOr(&s_gt1, 1);
    if (odd) atomicOr(&s_odd, 1);
    __syncthreads();
    if (threadIdx.x == 0) g_mask_byte_flag = (!s_gt1 && s_odd) ? 1 : 0;
}

__device__ __forceinline__ void split_store(__nv_bfloat16* hi, __nv_bfloat16* lo,
                                            size_t idx, float v) {
    __nv_bfloat16 h = __float2bfloat16(v);
    hi[idx] = h;
    lo[idx] = __float2bfloat16(v - __bfloat162float(h));
}

__global__ void build_x_kernel(const float* __restrict__ anchor,
                               const float* __restrict__ rnd,
                               const void*  __restrict__ mask) {
    int i = blockIdx.x * blockDim.x + threadIdx.x;
    const int n = BATCH * MDIM;
    if (i >= n) return;
    float a = anchor[i];
    split_store(g_Xhi, g_Xlo, i, a);
    bool m;
    if (g_mask_byte_flag) m = ((const unsigned char*)mask)[i] != 0;
    else                  m = ((const unsigned int*)mask)[i] != 0u;
    split_store(g_Xhi, g_Xlo, (size_t)n + i, m ? rnd[i] : a);
}

// ---------------------------------------------------------------------------
// Fused weight transpose + bf16 split for ALL 6 layers (grid.z = layer)
// ---------------------------------------------------------------------------
__global__ void wsplit_all_kernel(const float* __restrict__ enc_w0,
                                  const float* __restrict__ enc_w,
                                  const float* __restrict__ head_w) {
    const size_t HH = (size_t)HDIM * HDIM;
    const int z = blockIdx.z;
    const float* W;
    size_t off;
    int K;
    if (z == 0)      { W = enc_w0;                 off = 0;                      K = MDIM; }
    else if (z <= 3) { W = enc_w  + (z - 1) * HH;  off = 524288 + (z - 1) * HH;  K = HDIM; }
    else             { W = head_w + (z - 4) * HH;  off = 524288 + (z - 1) * HH;  K = HDIM; }
    if (blockIdx.y * 32 >= (unsigned)K) return;

    __shared__ float t[32][33];
    int nb = blockIdx.x * 32, kb = blockIdx.y * 32;
    int tx = threadIdx.x, ty = threadIdx.y;   // (32, 8)
    for (int r = ty; r < 32; r += 8)
        t[r][tx] = W[(size_t)(kb + r) * HDIM + nb + tx];
    __syncthreads();
    __nv_bfloat16* hi = g_Whi + off;
    __nv_bfloat16* lo = g_Wlo + off;
    for (int r = ty; r < 32; r += 8) {
        float v = t[tx][r];
        __nv_bfloat16 h = __float2bfloat16(v);
        __nv_bfloat16 l = __float2bfloat16(v - __bfloat162float(h));
        size_t o = (size_t)(nb + r) * K + kb + tx;
        hi[o] = h;  lo[o] = l;
    }
}

// ---------------------------------------------------------------------------
// HMMA GEMM: CTA 64x128, 128 threads = 4 warps (2m x 2n), warp tile 32x64,
// BK=64, 2-stage cp.async pipeline + intra-chunk fragment double buffering.
//   acc = Ah@Bh + Ah@Bl + Al@Bh   (pass-major MMA order: accumulator reuse
//   distance = 16 MMAs, hiding HMMA RAW latency)
// SMEM stage: Ah(8K) Al(8K) Bh(16K) Bl(16K) = 48KB; 2 stages = 96KB
//   => TWO CTAs co-resident per SM.
// ---------------------------------------------------------------------------
#define AH_OFF 0
#define AL_OFF 8192
#define BH_OFF 16384
#define BL_OFF 32768
#define STAGE_STRIDE 49152
#define SM_TOTAL (2 * STAGE_STRIDE)   // 98304

__global__ void __launch_bounds__(128, 2)
gemm_hmma(const __nv_bfloat16* __restrict__ Ahi,
          const __nv_bfloat16* __restrict__ Alo,
          const __nv_bfloat16* __restrict__ Bhi,
          const __nv_bfloat16* __restrict__ Blo,
          const float* __restrict__ bias,
          __nv_bfloat16* __restrict__ Chi,
          __nv_bfloat16* __restrict__ Clo,
          float* __restrict__ Cf32,
          int K, int writeF32) {
    extern __shared__ char smem[];
    const uint32_t sb = smem_u32(smem);
    const int tid  = threadIdx.x;
    const int wid  = tid >> 5, lane = tid & 31;
    const int wm   = wid & 1;          // warp m (2)
    const int wn   = wid >> 1;         // warp n (2)
    const int mb   = blockIdx.y, nb = blockIdx.x;

    const __nv_bfloat16* Ah = Ahi + (size_t)mb * 64 * K;
    const __nv_bfloat16* Al = Alo + (size_t)mb * 64 * K;
    const __nv_bfloat16* Bh = Bhi + (size_t)nb * 128 * K;
    const __nv_bfloat16* Bl = Blo + (size_t)nb * 128 * K;

    const int g8 = (tid & 7) * 8;

    float acc[2][8][4];
#pragma unroll
    for (int mt = 0; mt < 2; mt++)
#pragma unroll
        for (int nt = 0; nt < 8; nt++)
#pragma unroll
            for (int q = 0; q < 4; q++) acc[mt][nt][q] = 0.f;

    const int nchunks = K >> 6;

    auto issue_stage = [&](int c, int s) {
        const uint32_t bs = sb + s * STAGE_STRIDE;
        const int cc = c * 64 + g8;
        // A planes: 64 rows x 8 groups = 512 / 128 thr = 4 iters
#pragma unroll
        for (int j = 0; j < 4; j++) {
            int r = (tid + 128 * j) >> 3;
            uint32_t sw = SWZ128((uint32_t)(r * 128 + (tid & 7) * 16));
            CP_ASYNC16(bs + AH_OFF + sw, (const char*)(Ah + (size_t)r * K + cc));
            CP_ASYNC16(bs + AL_OFF + sw, (const char*)(Al + (size_t)r * K + cc));
        }
        // B planes: 128 rows x 8 groups = 1024 / 128 thr = 8 iters
#pragma unroll
        for (int j = 0; j < 8; j++) {
            int r = (tid + 128 * j) >> 3;
            uint32_t sw = SWZ128((uint32_t)(r * 128 + (tid & 7) * 16));
            CP_ASYNC16(bs + BH_OFF + sw, (const char*)(Bh + (size_t)r * K + cc));
            CP_ASYNC16(bs + BL_OFF + sw, (const char*)(Bl + (size_t)r * K + cc));
        }
    };

    issue_stage(0, 0); CP_COMMIT();
    if (nchunks > 1) issue_stage(1, 1);
    CP_COMMIT();

    // fragment double buffers
    uint32_t ah[2][2][4], al[2][2][4];   // [fb][mt][4]
    uint32_t bh[2][8][2], bl[2][8][2];   // [fb][nt][2]

    const int krow = lane & 15;
    const int kodd = (lane >> 4) * 8;

    auto load_frags = [&](uint32_t bufp, int ks, int fb) {
        const int kcB = (ks * 16 + kodd) * 2;
#pragma unroll
        for (int mt = 0; mt < 2; mt++) {
            uint32_t off = (uint32_t)((wm * 32 + mt * 16 + krow) * 128) + kcB;
            ldsm_x4(ah[fb][mt], bufp + AH_OFF + SWZ128(off));
            ldsm_x4(al[fb][mt], bufp + AL_OFF + SWZ128(off));
        }
#pragma unroll
        for (int bt = 0; bt < 4; bt++) {
            uint32_t off = (uint32_t)((wn * 64 + bt * 16 + krow) * 128) + kcB;
            uint32_t r[4], r2[4];
            ldsm_x4(r,  bufp + BH_OFF + SWZ128(off));
            ldsm_x4(r2, bufp + BL_OFF + SWZ128(off));
            bh[fb][2*bt][0] = r[0];  bh[fb][2*bt+1][0] = r[1];
            bh[fb][2*bt][1] = r[2];  bh[fb][2*bt+1][1] = r[3];
            bl[fb][2*bt][0] = r2[0]; bl[fb][2*bt+1][0] = r2[1];
            bl[fb][2*bt][1] = r2[2]; bl[fb][2*bt+1][1] = r2[3];
        }
    };

    for (int c = 0; c < nchunks; c++) {
        CP_WAIT1();              // stage c resident (stage c+1 may be pending)
        __syncthreads();

        const uint32_t bufp = sb + (c & 1) * STAGE_STRIDE;
        load_frags(bufp, 0, 0);
#pragma unroll
        for (int ks = 0; ks < 4; ks++) {
            const int fb = ks & 1;
            if (ks < 3) load_frags(bufp, ks + 1, fb ^ 1);
            // pass-major order: accumulator reuse distance = 16 MMAs
#pragma unroll
            for (int mt = 0; mt < 2; mt++)
#pragma unroll
                for (int nt = 0; nt < 8; nt++)
                    mma_bf16(acc[mt][nt], ah[fb][mt], bh[fb][nt][0], bh[fb][nt][1]);
#pragma unroll
            for (int mt = 0; mt < 2; mt++)
#pragma unroll
                for (int nt = 0; nt < 8; nt++)
                    mma_bf16(acc[mt][nt], ah[fb][mt], bl[fb][nt][0], bl[fb][nt][1]);
#pragma unroll
            for (int mt = 0; mt < 2; mt++)
#pragma unroll
                for (int nt = 0; nt < 8; nt++)
                    mma_bf16(acc[mt][nt], al[fb][mt], bh[fb][nt][0], bh[fb][nt][1]);
        }
        __syncthreads();         // everyone done reading buffer (c&1)
        if (c + 2 < nchunks) issue_stage(c + 2, c & 1);
        CP_COMMIT();
    }

    // ---- epilogue: relu(acc+bias); split bf16 planes or fp32 ----
    const int rbase = mb * 64 + wm * 32 + (lane >> 2);
    const int cbase = nb * 128 + wn * 64 + 2 * (lane & 3);
#pragma unroll
    for (int mt = 0; mt < 2; mt++)
#pragma unroll
        for (int nt = 0; nt < 8; nt++) {
            const int c0 = cbase + nt * 8;
            const float b0v = bias[c0], b1v = bias[c0 + 1];
            float v00 = fmaxf(acc[mt][nt][0] + b0v, 0.f);
            float v01 = fmaxf(acc[mt][nt][1] + b1v, 0.f);
            float v10 = fmaxf(acc[mt][nt][2] + b0v, 0.f);
            float v11 = fmaxf(acc[mt][nt][3] + b1v, 0.f);
            const size_t o0 = (size_t)(rbase + mt * 16)     * HDIM + c0;
            const size_t o1 = (size_t)(rbase + mt * 16 + 8) * HDIM + c0;
            if (writeF32) {
                *(float2*)(Cf32 + o0) = make_float2(v00, v01);
                *(float2*)(Cf32 + o1) = make_float2(v10, v11);
            } else {
                __nv_bfloat16 h00 = __float2bfloat16(v00);
                __nv_bfloat16 h01 = __float2bfloat16(v01);
                __nv_bfloat16 h10 = __float2bfloat16(v10);
                __nv_bfloat16 h11 = __float2bfloat16(v11);
                __nv_bfloat162 l0, l1;
                l0.x = __float2bfloat16(v00 - __bfloat162float(h00));
                l0.y = __float2bfloat16(v01 - __bfloat162float(h01));
                l1.x = __float2bfloat16(v10 - __bfloat162float(h10));
                l1.y = __float2bfloat16(v11 - __bfloat162float(h11));
                *(__nv_bfloat162*)(Chi + o0) = make_bfloat162(h00, h01);
                *(__nv_bfloat162*)(Chi + o1) = make_bfloat162(h10, h11);
                *(__nv_bfloat162*)(Clo + o0) = l0;
                *(__nv_bfloat162*)(Clo + o1) = l1;
            }
        }
}

// ---------------------------------------------------------------------------
// kernel_launch
// ---------------------------------------------------------------------------
extern "C" void kernel_launch(void* const* d_in, const int* in_sizes, int n_in,
                              void* d_out, int out_size) {
    const float* anchor = (const float*)d_in[0];
    const float* rnd    = (const float*)d_in[1];
    const void*  mask   = d_in[2];
    const float* enc_w0 = (const float*)d_in[3];
    const float* enc_b0 = (const float*)d_in[4];
    const float* enc_w  = (const float*)d_in[5];
    const float* enc_b  = (const float*)d_in[6];
    const float* head_w = (const float*)d_in[7];
    const float* head_b = (const float*)d_in[8];
    float* out = (float*)d_out;

    __nv_bfloat16 *Xhi, *Xlo, *A0hi, *A0lo, *A1hi, *A1lo, *Whi, *Wlo;
    cudaGetSymbolAddress((void**)&Xhi,  g_Xhi);
    cudaGetSymbolAddress((void**)&Xlo,  g_Xlo);
    cudaGetSymbolAddress((void**)&A0hi, g_A0hi);
    cudaGetSymbolAddress((void**)&A0lo, g_A0lo);
    cudaGetSymbolAddress((void**)&A1hi, g_A1hi);
    cudaGetSymbolAddress((void**)&A1lo, g_A1lo);
    cudaGetSymbolAddress((void**)&Whi,  g_Whi);
    cudaGetSymbolAddress((void**)&Wlo,  g_Wlo);

    cudaFuncSetAttribute(gemm_hmma, cudaFuncAttributeMaxDynamicSharedMemorySize, SM_TOTAL);

    detect_mask_kernel<<<1, 256>>>((const unsigned char*)mask);
    const int nSel = BATCH * MDIM;
    build_x_kernel<<<(nSel + 255) / 256, 256>>>(anchor, rnd, mask);

    dim3 wb(32, 8);
    wsplit_all_kernel<<<dim3(HDIM / 32, HDIM / 32, 6), wb>>>(enc_w0, enc_w, head_w);

    const size_t HH = (size_t)HDIM * HDIM;
    const size_t woff[6] = {0, 524288, 524288 + HH, 524288 + 2*HH, 524288 + 3*HH, 524288 + 4*HH};

    dim3 grid(HDIM / 128, ROWS / 64);   // (8, 256) = 2048 CTAs
    gemm_hmma<<<grid, 128, SM_TOTAL>>>(Xhi,  Xlo,  Whi + woff[0], Wlo + woff[0], enc_b0,          A0hi, A0lo, nullptr, MDIM, 0);
    gemm_hmma<<<grid, 128, SM_TOTAL>>>(A0hi, A0lo, Whi + woff[1], Wlo + woff[1], enc_b + 0*HDIM,  A1hi, A1lo, nullptr, HDIM, 0);
    gemm_hmma<<<grid, 128, SM_TOTAL>>>(A1hi, A1lo, Whi + woff[2], Wlo + woff[2], enc_b + 1*HDIM,  A0hi, A0lo, nullptr, HDIM, 0);
    gemm_hmma<<<grid, 128, SM_TOTAL>>>(A0hi, A0lo, Whi + woff[3], Wlo + woff[3], enc_b + 2*HDIM,  A1hi, A1lo, nullptr, HDIM, 0);
    gemm_hmma<<<grid, 128, SM_TOTAL>>>(A1hi, A1lo, Whi + woff[4], Wlo + woff[4], head_b + 0*HDIM, A0hi, A0lo, nullptr, HDIM, 0);
    gemm_hmma<<<grid, 128, SM_TOTAL>>>(A0hi, A0lo, Whi + woff[5], Wlo + woff[5], head_b + 1*HDIM, nullptr, nullptr, out, HDIM, 1);
}